// round 16
// baseline (speedup 1.0000x reference)
#include <cuda_runtime.h>
#include <cstdint>
#include <cstddef>

#define FULLMASK 0xffffffffu

constexpr int Bb  = 16;
constexpr int Nn  = 256;
constexpr int Hh  = 1024;
constexpr int HIDh= 300;
constexpr int Ll  = 64;
constexpr int Mm  = Bb * Nn;        // 4096
constexpr int KP  = 304;            // padded 301 -> 304
constexpr int NU  = Ll * KP;        // 19456 merged (l,j) columns of U

// ---------------- scratch ----------------
__device__ float g_d1  [Mm * KP];
__device__ float g_h1  [Mm * KP];
__device__ float g_U   [(size_t)Mm * NU];
__device__ float g_Wp  [(size_t)Ll * KP * KP];
__device__ float g_hist[(size_t)Mm * Nn * Ll];
__device__ float g_expT[Ll * Ll];
__device__ int   g_len [Bb];
__device__ float g_num [Mm];
__device__ float g_den [Mm];

#define FMA2(acc, a, b) asm("fma.rn.f32x2 %0, %1, %2, %0;" : "+l"(acc) : "l"(a), "l"(b))
#define ADD2(d, a, b)   asm("add.rn.f32x2 %0, %1, %2;" : "=l"(d) : "l"(a), "l"(b))
#define DUP2(d, f)      asm("mov.b64 %0, {%1, %1};" : "=l"(d) : "r"(__float_as_uint(f)))
#define UNPK2(lo, hi, s) do { unsigned _ulo, _uhi; \
    asm("mov.b64 {%0, %1}, %2;" : "=r"(_ulo), "=r"(_uhi) : "l"(s)); \
    lo = __uint_as_float(_ulo); hi = __uint_as_float(_uhi); } while(0)
#define PACK2(d, lo, hi) asm("mov.b64 %0, {%1, %2};" : "=l"(d) : "f"(lo), "f"(hi))

// ---------------- K0: mask probe, lengths, exp(trans) ----------------
__global__ void k_pre(const void* __restrict__ maskp, const float* __restrict__ trans) {
    int tid = threadIdx.x;
    __shared__ int fmt_s;
    if (tid == 0) {
        unsigned int w = *(const unsigned int*)maskp;
        int f = 0;
        if (w == 1u)               f = 1;
        else if (w == 0x3f800000u) f = 2;
        fmt_s = f;
    }
    __syncthreads();
    int fmt = fmt_s;
    if (tid < Bb) {
        int cnt = 0;
        for (int t = 0; t < Nn; t++) {
            bool v;
            if (fmt == 1)      v = ((const int*)maskp)[tid * Nn + t] != 0;
            else if (fmt == 2) v = ((const float*)maskp)[tid * Nn + t] != 0.f;
            else               v = ((const unsigned char*)maskp)[tid * Nn + t] != 0;
            cnt += v ? 1 : 0;
        }
        g_len[tid] = cnt;
    }
    for (int i = tid; i < Ll * Ll; i += blockDim.x) g_expT[i] = expf(trans[i]);
}

// ---------------- K0b: pad W [64][301][301] -> g_Wp [64][304][304] --------------
__global__ void k_padW(const float* __restrict__ W) {
    int idx  = blockIdx.x * 256 + threadIdx.x;
    int col4 = idx % 76;
    int row  = idx / 76;                 // l*304 + i
    int i = row % KP, l = row / KP;
    int j0 = col4 * 4;
    float4 v = make_float4(0.f, 0.f, 0.f, 0.f);
    if (i < 301) {
        const float* src = W + (size_t)l * 90601 + (size_t)i * 301;
        if (j0 + 0 < 301) v.x = src[j0 + 0];
        if (j0 + 1 < 301) v.y = src[j0 + 1];
        if (j0 + 2 < 301) v.z = src[j0 + 2];
        if (j0 + 3 < 301) v.w = src[j0 + 3];
    }
    *(float4*)&g_Wp[(size_t)row * KP + j0] = v;
}

// ======================================================================
// Proven GEMM: 128x128 block tile, 8 warps (4m x 2n), warp 32x64,
// thread 8m x 8n. KC=16 double-buffered.
// ======================================================================

#define GEMM_COMMON                                                        \
    __shared__ float As[2][16][128];                                       \
    __shared__ float Bs[2][16][132];                                       \
    const int tid  = threadIdx.x;                                          \
    const int lane = tid & 31, wid = tid >> 5;                             \
    const int mwb  = (wid & 3) * 32 + (lane >> 3) * 8;                     \
    const int nwb  = (wid >> 2) * 64 + (lane & 7) * 4;                     \
    const int ar   = tid >> 1, ak8 = (tid & 1) * 8;                        \
    unsigned long long acc[4][8];                                          \
    _Pragma("unroll") for (int p = 0; p < 4; p++)                          \
    _Pragma("unroll") for (int q = 0; q < 8; q++) acc[p][q] = 0ull;

#define STS_A16(B_)                                                        \
    { As[B_][ak8+0][ar] = ra0.x; As[B_][ak8+1][ar] = ra0.y;                \
      As[B_][ak8+2][ar] = ra0.z; As[B_][ak8+3][ar] = ra0.w;                \
      As[B_][ak8+4][ar] = ra1.x; As[B_][ak8+5][ar] = ra1.y;                \
      As[B_][ak8+6][ar] = ra1.z; As[B_][ak8+7][ar] = ra1.w; }

#define COMPUTE16(B_)                                                      \
    _Pragma("unroll")                                                      \
    for (int kk = 0; kk < 16; kk++) {                                      \
        ulonglong2 aA = *(const ulonglong2*)&As[B_][kk][mwb];              \
        ulonglong2 aB = *(const ulonglong2*)&As[B_][kk][mwb + 4];          \
        float4 b0 = *(const float4*)&Bs[B_][kk][nwb];                      \
        float4 b1 = *(const float4*)&Bs[B_][kk][nwb + 32];                 \
        float bf[8] = {b0.x, b0.y, b0.z, b0.w, b1.x, b1.y, b1.z, b1.w};    \
        _Pragma("unroll")                                                  \
        for (int q = 0; q < 8; q++) {                                      \
            unsigned long long bd; DUP2(bd, bf[q]);                        \
            FMA2(acc[0][q], aA.x, bd); FMA2(acc[1][q], aA.y, bd);          \
            FMA2(acc[2][q], aB.x, bd); FMA2(acc[3][q], aB.y, bd);          \
        }                                                                  \
    }

// ---------------- K1: fused MLP heads GEMM (M=4096, N=640(608), K=1024) --------
__global__ void __launch_bounds__(256, 2) k_mlp(const float* __restrict__ X,
                                                const float* __restrict__ Wh,
                                                const float* __restrict__ bh,
                                                const float* __restrict__ Wd,
                                                const float* __restrict__ bd) {
    const int n0 = blockIdx.x * 128, m0 = blockIdx.y * 128;
    GEMM_COMMON
    const float* Ap = &X[(size_t)(m0 + ar) * Hh + ak8];
    const int ty = tid >> 1, tk8 = (tid & 1) * 8;
    const int n  = n0 + ty;
    const int hd = n >= 304;
    const int c  = hd ? n - 304 : n;
    const bool bvalid = (n < 608) && (c < HIDh);
    const float* Bp = bvalid ? &(hd ? Wd : Wh)[(size_t)c * Hh + tk8] : nullptr;

    float4 ra0, ra1, rb0, rb1;
    ra0 = *(const float4*)Ap; ra1 = *(const float4*)(Ap + 4);
    rb0 = rb1 = make_float4(0.f, 0.f, 0.f, 0.f);
    if (bvalid) { rb0 = *(const float4*)Bp; rb1 = *(const float4*)(Bp + 4); }
    STS_A16(0)
    { float bv[8] = {rb0.x, rb0.y, rb0.z, rb0.w, rb1.x, rb1.y, rb1.z, rb1.w};
#pragma unroll
      for (int i = 0; i < 8; i++) Bs[0][tk8 + i][ty] = bv[i]; }
    __syncthreads();
    int buf = 0;
    for (int kc = 0; kc < Hh; kc += 16) {
        bool more = (kc + 16) < Hh;
        if (more) {
            ra0 = *(const float4*)(Ap + kc + 16); ra1 = *(const float4*)(Ap + kc + 20);
            if (bvalid) { rb0 = *(const float4*)(Bp + kc + 16); rb1 = *(const float4*)(Bp + kc + 20); }
        }
        COMPUTE16(buf)
        if (more) {
            STS_A16(buf ^ 1)
            float bv[8] = {rb0.x, rb0.y, rb0.z, rb0.w, rb1.x, rb1.y, rb1.z, rb1.w};
#pragma unroll
            for (int i = 0; i < 8; i++) Bs[buf ^ 1][tk8 + i][ty] = bv[i];
        }
        __syncthreads();
        buf ^= 1;
    }
#pragma unroll
    for (int p = 0; p < 4; p++) {
        int m = m0 + mwb + 2 * p;
#pragma unroll
        for (int g = 0; g < 2; g++) {
            int cbase = n0 + nwb + g * 32;
            if (cbase >= 608) continue;
            int gh = cbase >= 304;
            int cc0 = gh ? cbase - 304 : cbase;
            float* dst = gh ? g_d1 : g_h1;
            const float* bias = gh ? bd : bh;
#pragma unroll
            for (int i = 0; i < 4; i++) {
                float lo, hi; UNPK2(lo, hi, acc[p][g * 4 + i]);
                int cc = cc0 + i;
                float o0, o1;
                if (cc < HIDh)       { float bv = bias[cc]; o0 = fmaxf(lo + bv, 0.f); o1 = fmaxf(hi + bv, 0.f); }
                else if (cc == HIDh) { o0 = o1 = 1.f; }
                else                 { o0 = o1 = 0.f; }
                dst[(size_t)m * KP + cc]       = o0;
                dst[(size_t)(m + 1) * KP + cc] = o1;
            }
        }
    }
}

// ---------------- K2: U = d1 @ Wp  (M=4096, N=19456, K=304) ----------------
__global__ void __launch_bounds__(256, 2) k_gemmU() {
    const int n0 = blockIdx.x * 128, m0 = blockIdx.y * 128;
    GEMM_COMMON
    const float* Ap = &g_d1[(size_t)(m0 + ar) * KP + ak8];
    const int kq = tid >> 4, n8 = (tid & 15) * 8;      // B: 16 k-rows x 16 col-groups
    const int col0 = n0 + n8;
    const int l = col0 / KP, j0 = col0 - l * KP;       // 8-col group never straddles l
    const float* Bp = &g_Wp[((size_t)l * KP) * KP + j0];

    float4 ra0, ra1, rb0, rb1;
    ra0 = *(const float4*)Ap; ra1 = *(const float4*)(Ap + 4);
    rb0 = *(const float4*)(Bp + (size_t)kq * KP);
    rb1 = *(const float4*)(Bp + (size_t)kq * KP + 4);
    STS_A16(0)
    *(float4*)&Bs[0][kq][n8]     = rb0;
    *(float4*)&Bs[0][kq][n8 + 4] = rb1;
    __syncthreads();
    int buf = 0;
    for (int kc = 0; kc < KP; kc += 16) {
        bool more = (kc + 16) < KP;
        if (more) {
            ra0 = *(const float4*)(Ap + kc + 16); ra1 = *(const float4*)(Ap + kc + 20);
            rb0 = *(const float4*)(Bp + (size_t)(kc + 16 + kq) * KP);
            rb1 = *(const float4*)(Bp + (size_t)(kc + 16 + kq) * KP + 4);
        }
        COMPUTE16(buf)
        if (more) {
            STS_A16(buf ^ 1)
            *(float4*)&Bs[buf ^ 1][kq][n8]     = rb0;
            *(float4*)&Bs[buf ^ 1][kq][n8 + 4] = rb1;
        }
        __syncthreads();
        buf ^= 1;
    }
#pragma unroll
    for (int p = 0; p < 4; p++) {
        int m = m0 + mwb + 2 * p;
        float* u0 = &g_U[(size_t)m * NU];
        float* u1 = &g_U[(size_t)(m + 1) * NU];
        float lo0, hi0, lo1, hi1, lo2, hi2, lo3, hi3;
        UNPK2(lo0, hi0, acc[p][0]); UNPK2(lo1, hi1, acc[p][1]);
        UNPK2(lo2, hi2, acc[p][2]); UNPK2(lo3, hi3, acc[p][3]);
        *(float4*)&u0[n0 + nwb] = make_float4(lo0, lo1, lo2, lo3);
        *(float4*)&u1[n0 + nwb] = make_float4(hi0, hi1, hi2, hi3);
        UNPK2(lo0, hi0, acc[p][4]); UNPK2(lo1, hi1, acc[p][5]);
        UNPK2(lo2, hi2, acc[p][6]); UNPK2(lo3, hi3, acc[p][7]);
        *(float4*)&u0[n0 + nwb + 32] = make_float4(lo0, lo1, lo2, lo3);
        *(float4*)&u1[n0 + nwb + 32] = make_float4(hi0, hi1, hi2, hi3);
    }
}

// ---------------- K3: S per batch (M=16384, N=256, K=304) -------------------
__global__ void __launch_bounds__(256, 2) k_gemmS(float* __restrict__ sout) {
    const int b  = blockIdx.z;
    const int n0 = blockIdx.x * 128, m0 = blockIdx.y * 128;
    GEMM_COMMON
    const float* Ap = &g_U[(size_t)(b * 16384 + m0 + ar) * KP + ak8];
    const int ty = tid >> 1, tk8 = (tid & 1) * 8;
    const float* Bp = &g_h1[(size_t)(b * 256 + n0 + ty) * KP + tk8];

    float4 ra0, ra1, rb0, rb1;
    ra0 = *(const float4*)Ap; ra1 = *(const float4*)(Ap + 4);
    rb0 = *(const float4*)Bp; rb1 = *(const float4*)(Bp + 4);
    STS_A16(0)
    { float bv[8] = {rb0.x, rb0.y, rb0.z, rb0.w, rb1.x, rb1.y, rb1.z, rb1.w};
#pragma unroll
      for (int i = 0; i < 8; i++) Bs[0][tk8 + i][ty] = bv[i]; }
    __syncthreads();
    int buf = 0;
    for (int kc = 0; kc < KP; kc += 16) {
        bool more = (kc + 16) < KP;
        if (more) {
            ra0 = *(const float4*)(Ap + kc + 16); ra1 = *(const float4*)(Ap + kc + 20);
            rb0 = *(const float4*)(Bp + kc + 16); rb1 = *(const float4*)(Bp + kc + 20);
        }
        COMPUTE16(buf)
        if (more) {
            STS_A16(buf ^ 1)
            float bv[8] = {rb0.x, rb0.y, rb0.z, rb0.w, rb1.x, rb1.y, rb1.z, rb1.w};
#pragma unroll
            for (int i = 0; i < 8; i++) Bs[buf ^ 1][tk8 + i][ty] = bv[i];
        }
        __syncthreads();
        buf ^= 1;
    }
#pragma unroll
    for (int p = 0; p < 4; p++) {
        int R = m0 + mwb + 2 * p;
        int x = R >> 6, l = R & 63;
        size_t base = ((size_t)(b * 256 + x) * 256) * 64;
#pragma unroll
        for (int q = 0; q < 8; q++) {
            float lo, hi; UNPK2(lo, hi, acc[p][q]);
            int y = n0 + nwb + (q < 4 ? q : 28 + q);
            sout[base + (size_t)y * 64 + l]     = lo;
            sout[base + (size_t)y * 64 + l + 1] = hi;
        }
    }
}

// ---------------- K6: fused log_softmax + forward + Viterbi + numerator ------
// Per j: LDS.128 (t-pair/e-pair as ulonglong2 halves) + FMA2 (forward q)
// + ADD2 (v+T packed) + mov-split + 2 fmaxf (no packed max on sm_100a).
// startT/endT read from global (once per thread) to keep smem at 48KB exactly.
// Same operand values and q-order as R13 -> hist/den/decoded bit-identical.
__global__ void __launch_bounds__(256) k_scan(const float* __restrict__ sflat,
                                              const int* __restrict__ labels,
                                              const float* __restrict__ trans,
                                              const float* __restrict__ startT,
                                              const float* __restrict__ endT) {
    __shared__ float4 sTE[64 * 32];       // 32 KB
    __shared__ float pbuf[8][2][128];     // 8 KB  dup'd p
    __shared__ float vbuf[8][2][128];     // 8 KB  dup'd v   -> total 48 KB
    int tid = threadIdx.x;
    for (int i = tid; i < 2048; i += 256) {
        int j = i >> 5, kp = (i & 31) * 2;
        sTE[i] = make_float4(trans[j * 64 + kp], trans[j * 64 + kp + 1],
                             g_expT[j * 64 + kp], g_expT[j * 64 + kp + 1]);
    }
    __syncthreads();
    int w = tid >> 5, lane = tid & 31;
    int m = blockIdx.x * 8 + w;
    int k0 = 2 * lane;
    int len = g_len[m >> 8];
    const float* sp   = sflat + (size_t)m * Nn * Ll;
    const int*   tg   = labels + m * Nn;
    float*       hist = g_hist + (size_t)m * Nn * Ll;
    float a0, a1, v0, v1;
    float num;
    int prev;
    {   // t = 0
        float s0 = sp[k0], s1 = sp[k0 + 1];
        float se = __expf(s0) + __expf(s1);
#pragma unroll
        for (int o = 16; o; o >>= 1) se += __shfl_xor_sync(FULLMASK, se, o);
        float lse = __logf(se);
        prev = tg[0];
        float cand = (prev & 1) ? s1 : s0;
        float sv = __shfl_sync(FULLMASK, cand, prev >> 1);
        num = startT[prev] + (sv - lse);
        float st0 = startT[k0], st1 = startT[k0 + 1];
        a0 = st0 + (s0 - lse); a1 = st1 + (s1 - lse);
        v0 = a0; v1 = a1;
        *(float2*)&hist[k0] = make_float2(v0, v1);
    }
    for (int t = 1; t < len; t++) {
        float s0 = sp[t * 64 + k0], s1 = sp[t * 64 + k0 + 1];
        float se = __expf(s0) + __expf(s1);
#pragma unroll
        for (int o = 16; o; o >>= 1) se += __shfl_xor_sync(FULLMASK, se, o);
        float lse = __logf(se);
        // numerator (gold path)
        int tt = tg[t];
        float cand = (tt & 1) ? s1 : s0;
        float sv = __shfl_sync(FULLMASK, cand, tt >> 1);
        float4 teg = sTE[prev * 32 + (tt >> 1)];
        num += (sv - lse) + ((tt & 1) ? teg.y : teg.x);
        prev = tt;
        float etx = s0 - lse, ety = s1 - lse;
        // forward shift
        float mx = fmaxf(a0, a1);
#pragma unroll
        for (int o = 16; o; o >>= 1) mx = fmaxf(mx, __shfl_xor_sync(FULLMASK, mx, o));
        float p0 = __expf(a0 - mx), p1 = __expf(a1 - mx);
        int pb = t & 1;
        *(float4*)&pbuf[w][pb][4 * lane] = make_float4(p0, p0, p1, p1);
        *(float4*)&vbuf[w][pb][4 * lane] = make_float4(v0, v0, v1, v1);
        __syncwarp();
        unsigned long long q = 0ull;
        float b0 = -1e30f, b1 = -1e30f;
#pragma unroll
        for (int jj = 0; jj < 16; jj++) {
            ulonglong2 vd0 = *(const ulonglong2*)&vbuf[w][pb][8 * jj];
            ulonglong2 vd1 = *(const ulonglong2*)&vbuf[w][pb][8 * jj + 4];
            ulonglong2 pd0 = *(const ulonglong2*)&pbuf[w][pb][8 * jj];
            ulonglong2 pd1 = *(const ulonglong2*)&pbuf[w][pb][8 * jj + 4];
            int j0 = 4 * jj;
            unsigned long long tmp; float c0, c1;
            {
                ulonglong2 te = *(const ulonglong2*)&sTE[(j0 + 0) * 32 + lane];
                FMA2(q, pd0.x, te.y);
                ADD2(tmp, vd0.x, te.x); UNPK2(c0, c1, tmp);
                b0 = fmaxf(b0, c0); b1 = fmaxf(b1, c1);
            }
            {
                ulonglong2 te = *(const ulonglong2*)&sTE[(j0 + 1) * 32 + lane];
                FMA2(q, pd0.y, te.y);
                ADD2(tmp, vd0.y, te.x); UNPK2(c0, c1, tmp);
                b0 = fmaxf(b0, c0); b1 = fmaxf(b1, c1);
            }
            {
                ulonglong2 te = *(const ulonglong2*)&sTE[(j0 + 2) * 32 + lane];
                FMA2(q, pd1.x, te.y);
                ADD2(tmp, vd1.x, te.x); UNPK2(c0, c1, tmp);
                b0 = fmaxf(b0, c0); b1 = fmaxf(b1, c1);
            }
            {
                ulonglong2 te = *(const ulonglong2*)&sTE[(j0 + 3) * 32 + lane];
                FMA2(q, pd1.y, te.y);
                ADD2(tmp, vd1.y, te.x); UNPK2(c0, c1, tmp);
                b0 = fmaxf(b0, c0); b1 = fmaxf(b1, c1);
            }
        }
        float q0, q1; UNPK2(q0, q1, q);
        v0 = b0 + etx; v1 = b1 + ety;
        a0 = mx + __logf(q0) + etx;
        a1 = mx + __logf(q1) + ety;
        *(float2*)&hist[t * 64 + k0] = make_float2(v0, v1);
    }
    // den + num writeback (endT from global, once)
    float z0 = a0 + endT[k0], z1 = a1 + endT[k0 + 1];
    float mx = fmaxf(z0, z1);
#pragma unroll
    for (int o = 16; o; o >>= 1) mx = fmaxf(mx, __shfl_xor_sync(FULLMASK, mx, o));
    float e = __expf(z0 - mx) + __expf(z1 - mx);
#pragma unroll
    for (int o = 16; o; o >>= 1) e += __shfl_xor_sync(FULLMASK, e, o);
    if (lane == 0) {
        g_den[m] = mx + __logf(e);
        g_num[m] = num + endT[prev];
    }
}

// ---------------- K7: Viterbi backtrace ----------------
__global__ void __launch_bounds__(256) k_bt(const float* __restrict__ trans,
                                            const float* __restrict__ endT,
                                            float* __restrict__ dec_out) {
    __shared__ float sT[64 * 65];
    __shared__ float sEn[64];
    int tid = threadIdx.x;
    for (int i = tid; i < 4096; i += 256) { int j = i >> 6, k = i & 63; sT[j * 65 + k] = trans[i]; }
    if (tid < 64) sEn[tid] = endT[tid];
    __syncthreads();
    int m = blockIdx.x * 8 + (tid >> 5), lane = tid & 31, k1 = lane, k2 = lane + 32;
    int len = g_len[m >> 8];
    const float* hist = g_hist + (size_t)m * Nn * Ll;
    float* dec = dec_out + (size_t)m * Nn;
    float f1 = hist[(len - 1) * 64 + k1] + sEn[k1];
    float f2 = hist[(len - 1) * 64 + k2] + sEn[k2];
    float bv; int bi;
    if (f2 > f1) { bv = f2; bi = k2; } else { bv = f1; bi = k1; }
#pragma unroll
    for (int o = 16; o; o >>= 1) {
        float ov = __shfl_xor_sync(FULLMASK, bv, o);
        int   oi = __shfl_xor_sync(FULLMASK, bi, o);
        if (ov > bv || (ov == bv && oi < bi)) { bv = ov; bi = oi; }
    }
    int cur = bi;
    for (int j = len - 1 + lane; j < Nn; j += 32) dec[j] = (float)cur;
    for (int t = len - 1; t >= 1; t--) {
        float h1v = hist[(t - 1) * 64 + k1] + sT[k1 * 65 + cur];
        float h2v = hist[(t - 1) * 64 + k2] + sT[k2 * 65 + cur];
        float bv2; int bi2;
        if (h2v > h1v) { bv2 = h2v; bi2 = k2; } else { bv2 = h1v; bi2 = k1; }
#pragma unroll
        for (int o = 16; o; o >>= 1) {
            float ov = __shfl_xor_sync(FULLMASK, bv2, o);
            int   oi = __shfl_xor_sync(FULLMASK, bi2, o);
            if (ov > bv2 || (ov == bv2 && oi < bi2)) { bv2 = ov; bi2 = oi; }
        }
        cur = bi2;
        if (lane == 0) dec[t - 1] = (float)cur;
    }
}

// ---------------- K8: loss reduction ----------------
__global__ void k_loss(float* __restrict__ out) {
    __shared__ float sm[256];
    int tid = threadIdx.x;
    float s = 0.f;
    for (int i = 0; i < 16; i++) {
        int m = tid * 16 + i;
        bool w = (m & 255) < g_len[m >> 8];
        if (w) s += g_num[m] - g_den[m];
    }
    sm[tid] = s;
    __syncthreads();
    for (int st = 128; st; st >>= 1) { if (tid < st) sm[tid] += sm[tid + st]; __syncthreads(); }
    if (tid == 0) out[0] = -sm[0];
}

// ---------------- launch ----------------
extern "C" void kernel_launch(void* const* d_in, const int* in_sizes, int n_in,
                              void* d_out, int out_size) {
    (void)in_sizes; (void)n_in; (void)out_size;
    const float* input  = (const float*)d_in[0];
    const void*  mask   = d_in[1];
    const int*   labels = (const int*)d_in[2];
    const float* Wh     = (const float*)d_in[3];
    const float* bh     = (const float*)d_in[4];
    const float* Wd     = (const float*)d_in[5];
    const float* bd     = (const float*)d_in[6];
    const float* Wb     = (const float*)d_in[7];
    const float* startT = (const float*)d_in[8];
    const float* trans  = (const float*)d_in[9];
    const float* endT   = (const float*)d_in[10];

    float* out     = (float*)d_out;
    float* s_out   = out + 1;
    float* dec_out = out + 1 + (size_t)Mm * Nn * Ll;

    k_pre  <<<1, 256>>>(mask, trans);
    k_padW <<<5776, 256>>>(Wb);
    k_mlp  <<<dim3(5, 32),       256>>>(input, Wh, bh, Wd, bd);
    k_gemmU<<<dim3(152, 32),     256>>>();
    k_gemmS<<<dim3(2, 128, 16),  256>>>(s_out);
    k_scan <<<512, 256>>>(s_out, labels, trans, startT, endT);
    k_bt   <<<512, 256>>>(trans, endT, dec_out);
    k_loss <<<1, 256>>>(out);
}

// round 17
// speedup vs baseline: 1.0388x; 1.0388x over previous
#include <cuda_runtime.h>
#include <cstdint>
#include <cstddef>

#define FULLMASK 0xffffffffu

constexpr int Bb  = 16;
constexpr int Nn  = 256;
constexpr int Hh  = 1024;
constexpr int HIDh= 300;
constexpr int Ll  = 64;
constexpr int Mm  = Bb * Nn;        // 4096
constexpr int KP  = 304;            // padded 301 -> 304
constexpr int NU  = Ll * KP;        // 19456 merged (l,j) columns of U

// ---------------- scratch ----------------
__device__ float g_d1  [Mm * KP];
__device__ float g_h1  [Mm * KP];
__device__ float g_U   [(size_t)Mm * NU];
__device__ float g_Wp  [(size_t)Ll * KP * KP];
__device__ float g_hist[(size_t)Mm * Nn * Ll];
__device__ float g_expT[Ll * Ll];
__device__ int   g_len [Bb];
__device__ float g_num [Mm];
__device__ float g_den [Mm];

#define FMA2(acc, a, b) asm("fma.rn.f32x2 %0, %1, %2, %0;" : "+l"(acc) : "l"(a), "l"(b))
#define DUP2(d, f)      asm("mov.b64 %0, {%1, %1};" : "=l"(d) : "r"(__float_as_uint(f)))
#define UNPK2(lo, hi, s) do { unsigned _ulo, _uhi; \
    asm("mov.b64 {%0, %1}, %2;" : "=r"(_ulo), "=r"(_uhi) : "l"(s)); \
    lo = __uint_as_float(_ulo); hi = __uint_as_float(_uhi); } while(0)
#define PACK2(d, lo, hi) asm("mov.b64 %0, {%1, %2};" : "=l"(d) : "f"(lo), "f"(hi))

// ---------------- K0: mask probe, lengths, exp(trans) ----------------
__global__ void k_pre(const void* __restrict__ maskp, const float* __restrict__ trans) {
    int tid = threadIdx.x;
    __shared__ int fmt_s;
    if (tid == 0) {
        unsigned int w = *(const unsigned int*)maskp;
        int f = 0;
        if (w == 1u)               f = 1;
        else if (w == 0x3f800000u) f = 2;
        fmt_s = f;
    }
    __syncthreads();
    int fmt = fmt_s;
    if (tid < Bb) {
        int cnt = 0;
        for (int t = 0; t < Nn; t++) {
            bool v;
            if (fmt == 1)      v = ((const int*)maskp)[tid * Nn + t] != 0;
            else if (fmt == 2) v = ((const float*)maskp)[tid * Nn + t] != 0.f;
            else               v = ((const unsigned char*)maskp)[tid * Nn + t] != 0;
            cnt += v ? 1 : 0;
        }
        g_len[tid] = cnt;
    }
    for (int i = tid; i < Ll * Ll; i += blockDim.x) g_expT[i] = expf(trans[i]);
}

// ======================================================================
// Proven GEMM: 128x128 block tile, 8 warps (4m x 2n), warp 32x64,
// thread 8m x 8n. KC=16 double-buffered.
// ======================================================================

#define GEMM_COMMON                                                        \
    __shared__ float As[2][16][128];                                       \
    __shared__ float Bs[2][16][132];                                       \
    const int tid  = threadIdx.x;                                          \
    const int lane = tid & 31, wid = tid >> 5;                             \
    const int mwb  = (wid & 3) * 32 + (lane >> 3) * 8;                     \
    const int nwb  = (wid >> 2) * 64 + (lane & 7) * 4;                     \
    const int ar   = tid >> 1, ak8 = (tid & 1) * 8;                        \
    unsigned long long acc[4][8];                                          \
    _Pragma("unroll") for (int p = 0; p < 4; p++)                          \
    _Pragma("unroll") for (int q = 0; q < 8; q++) acc[p][q] = 0ull;

#define STS_A16(B_)                                                        \
    { As[B_][ak8+0][ar] = ra0.x; As[B_][ak8+1][ar] = ra0.y;                \
      As[B_][ak8+2][ar] = ra0.z; As[B_][ak8+3][ar] = ra0.w;                \
      As[B_][ak8+4][ar] = ra1.x; As[B_][ak8+5][ar] = ra1.y;                \
      As[B_][ak8+6][ar] = ra1.z; As[B_][ak8+7][ar] = ra1.w; }

#define COMPUTE16(B_)                                                      \
    _Pragma("unroll")                                                      \
    for (int kk = 0; kk < 16; kk++) {                                      \
        ulonglong2 aA = *(const ulonglong2*)&As[B_][kk][mwb];              \
        ulonglong2 aB = *(const ulonglong2*)&As[B_][kk][mwb + 4];          \
        float4 b0 = *(const float4*)&Bs[B_][kk][nwb];                      \
        float4 b1 = *(const float4*)&Bs[B_][kk][nwb + 32];                 \
        float bf[8] = {b0.x, b0.y, b0.z, b0.w, b1.x, b1.y, b1.z, b1.w};    \
        _Pragma("unroll")                                                  \
        for (int q = 0; q < 8; q++) {                                      \
            unsigned long long bd; DUP2(bd, bf[q]);                        \
            FMA2(acc[0][q], aA.x, bd); FMA2(acc[1][q], aA.y, bd);          \
            FMA2(acc[2][q], aB.x, bd); FMA2(acc[3][q], aB.y, bd);          \
        }                                                                  \
    }

// ---------------- K1: fused MLP-heads GEMM + W padding (merged launch) --------
// Blocks [0,160): MLP GEMM tiles (M=4096, N=640(608), K=1024).
// Blocks [160, 160+5776): pad bilinear_W [64][301][301] -> g_Wp [64][304][304].
// Both only feed k_gemmU/k_gemmS; internal order irrelevant. Overlaps the
// DRAM-bound pad with the FMA-bound GEMM.
__global__ void __launch_bounds__(256, 2) k_mlp(const float* __restrict__ X,
                                                const float* __restrict__ Wh,
                                                const float* __restrict__ bh,
                                                const float* __restrict__ Wd,
                                                const float* __restrict__ bd,
                                                const float* __restrict__ W) {
    if (blockIdx.x >= 160) {
        // ---- padW branch ----
        int idx  = (blockIdx.x - 160) * 256 + threadIdx.x;   // float4 index
        int col4 = idx % 76;
        int row  = idx / 76;                 // l*304 + i
        int i = row % KP, l = row / KP;
        int j0 = col4 * 4;
        float4 v = make_float4(0.f, 0.f, 0.f, 0.f);
        if (i < 301) {
            const float* src = W + (size_t)l * 90601 + (size_t)i * 301;
            if (j0 + 0 < 301) v.x = src[j0 + 0];
            if (j0 + 1 < 301) v.y = src[j0 + 1];
            if (j0 + 2 < 301) v.z = src[j0 + 2];
            if (j0 + 3 < 301) v.w = src[j0 + 3];
        }
        *(float4*)&g_Wp[(size_t)row * KP + j0] = v;
        return;
    }
    // ---- MLP GEMM branch ----
    const int n0 = (blockIdx.x % 5) * 128, m0 = (blockIdx.x / 5) * 128;
    GEMM_COMMON
    const float* Ap = &X[(size_t)(m0 + ar) * Hh + ak8];
    const int ty = tid >> 1, tk8 = (tid & 1) * 8;
    const int n  = n0 + ty;
    const int hd = n >= 304;
    const int c  = hd ? n - 304 : n;
    const bool bvalid = (n < 608) && (c < HIDh);
    const float* Bp = bvalid ? &(hd ? Wd : Wh)[(size_t)c * Hh + tk8] : nullptr;

    float4 ra0, ra1, rb0, rb1;
    ra0 = *(const float4*)Ap; ra1 = *(const float4*)(Ap + 4);
    rb0 = rb1 = make_float4(0.f, 0.f, 0.f, 0.f);
    if (bvalid) { rb0 = *(const float4*)Bp; rb1 = *(const float4*)(Bp + 4); }
    STS_A16(0)
    { float bv[8] = {rb0.x, rb0.y, rb0.z, rb0.w, rb1.x, rb1.y, rb1.z, rb1.w};
#pragma unroll
      for (int i = 0; i < 8; i++) Bs[0][tk8 + i][ty] = bv[i]; }
    __syncthreads();
    int buf = 0;
    for (int kc = 0; kc < Hh; kc += 16) {
        bool more = (kc + 16) < Hh;
        if (more) {
            ra0 = *(const float4*)(Ap + kc + 16); ra1 = *(const float4*)(Ap + kc + 20);
            if (bvalid) { rb0 = *(const float4*)(Bp + kc + 16); rb1 = *(const float4*)(Bp + kc + 20); }
        }
        COMPUTE16(buf)
        if (more) {
            STS_A16(buf ^ 1)
            float bv[8] = {rb0.x, rb0.y, rb0.z, rb0.w, rb1.x, rb1.y, rb1.z, rb1.w};
#pragma unroll
            for (int i = 0; i < 8; i++) Bs[buf ^ 1][tk8 + i][ty] = bv[i];
        }
        __syncthreads();
        buf ^= 1;
    }
#pragma unroll
    for (int p = 0; p < 4; p++) {
        int m = m0 + mwb + 2 * p;
#pragma unroll
        for (int g = 0; g < 2; g++) {
            int cbase = n0 + nwb + g * 32;
            if (cbase >= 608) continue;
            int gh = cbase >= 304;
            int cc0 = gh ? cbase - 304 : cbase;
            float* dst = gh ? g_d1 : g_h1;
            const float* bias = gh ? bd : bh;
#pragma unroll
            for (int i = 0; i < 4; i++) {
                float lo, hi; UNPK2(lo, hi, acc[p][g * 4 + i]);
                int cc = cc0 + i;
                float o0, o1;
                if (cc < HIDh)       { float bv = bias[cc]; o0 = fmaxf(lo + bv, 0.f); o1 = fmaxf(hi + bv, 0.f); }
                else if (cc == HIDh) { o0 = o1 = 1.f; }
                else                 { o0 = o1 = 0.f; }
                dst[(size_t)m * KP + cc]       = o0;
                dst[(size_t)(m + 1) * KP + cc] = o1;
            }
        }
    }
}

// ---------------- K2: U = d1 @ Wp  (M=4096, N=19456, K=304) ----------------
__global__ void __launch_bounds__(256, 2) k_gemmU() {
    const int n0 = blockIdx.x * 128, m0 = blockIdx.y * 128;
    GEMM_COMMON
    const float* Ap = &g_d1[(size_t)(m0 + ar) * KP + ak8];
    const int kq = tid >> 4, n8 = (tid & 15) * 8;      // B: 16 k-rows x 16 col-groups
    const int col0 = n0 + n8;
    const int l = col0 / KP, j0 = col0 - l * KP;       // 8-col group never straddles l
    const float* Bp = &g_Wp[((size_t)l * KP) * KP + j0];

    float4 ra0, ra1, rb0, rb1;
    ra0 = *(const float4*)Ap; ra1 = *(const float4*)(Ap + 4);
    rb0 = *(const float4*)(Bp + (size_t)kq * KP);
    rb1 = *(const float4*)(Bp + (size_t)kq * KP + 4);
    STS_A16(0)
    *(float4*)&Bs[0][kq][n8]     = rb0;
    *(float4*)&Bs[0][kq][n8 + 4] = rb1;
    __syncthreads();
    int buf = 0;
    for (int kc = 0; kc < KP; kc += 16) {
        bool more = (kc + 16) < KP;
        if (more) {
            ra0 = *(const float4*)(Ap + kc + 16); ra1 = *(const float4*)(Ap + kc + 20);
            rb0 = *(const float4*)(Bp + (size_t)(kc + 16 + kq) * KP);
            rb1 = *(const float4*)(Bp + (size_t)(kc + 16 + kq) * KP + 4);
        }
        COMPUTE16(buf)
        if (more) {
            STS_A16(buf ^ 1)
            *(float4*)&Bs[buf ^ 1][kq][n8]     = rb0;
            *(float4*)&Bs[buf ^ 1][kq][n8 + 4] = rb1;
        }
        __syncthreads();
        buf ^= 1;
    }
#pragma unroll
    for (int p = 0; p < 4; p++) {
        int m = m0 + mwb + 2 * p;
        float* u0 = &g_U[(size_t)m * NU];
        float* u1 = &g_U[(size_t)(m + 1) * NU];
        float lo0, hi0, lo1, hi1, lo2, hi2, lo3, hi3;
        UNPK2(lo0, hi0, acc[p][0]); UNPK2(lo1, hi1, acc[p][1]);
        UNPK2(lo2, hi2, acc[p][2]); UNPK2(lo3, hi3, acc[p][3]);
        *(float4*)&u0[n0 + nwb] = make_float4(lo0, lo1, lo2, lo3);
        *(float4*)&u1[n0 + nwb] = make_float4(hi0, hi1, hi2, hi3);
        UNPK2(lo0, hi0, acc[p][4]); UNPK2(lo1, hi1, acc[p][5]);
        UNPK2(lo2, hi2, acc[p][6]); UNPK2(lo3, hi3, acc[p][7]);
        *(float4*)&u0[n0 + nwb + 32] = make_float4(lo0, lo1, lo2, lo3);
        *(float4*)&u1[n0 + nwb + 32] = make_float4(hi0, hi1, hi2, hi3);
    }
}

// ---------------- K3: S per batch (M=16384, N=256, K=304) -------------------
__global__ void __launch_bounds__(256, 2) k_gemmS(float* __restrict__ sout) {
    const int b  = blockIdx.z;
    const int n0 = blockIdx.x * 128, m0 = blockIdx.y * 128;
    GEMM_COMMON
    const float* Ap = &g_U[(size_t)(b * 16384 + m0 + ar) * KP + ak8];
    const int ty = tid >> 1, tk8 = (tid & 1) * 8;
    const float* Bp = &g_h1[(size_t)(b * 256 + n0 + ty) * KP + tk8];

    float4 ra0, ra1, rb0, rb1;
    ra0 = *(const float4*)Ap; ra1 = *(const float4*)(Ap + 4);
    rb0 = *(const float4*)Bp; rb1 = *(const float4*)(Bp + 4);
    STS_A16(0)
    { float bv[8] = {rb0.x, rb0.y, rb0.z, rb0.w, rb1.x, rb1.y, rb1.z, rb1.w};
#pragma unroll
      for (int i = 0; i < 8; i++) Bs[0][tk8 + i][ty] = bv[i]; }
    __syncthreads();
    int buf = 0;
    for (int kc = 0; kc < KP; kc += 16) {
        bool more = (kc + 16) < KP;
        if (more) {
            ra0 = *(const float4*)(Ap + kc + 16); ra1 = *(const float4*)(Ap + kc + 20);
            rb0 = *(const float4*)(Bp + kc + 16); rb1 = *(const float4*)(Bp + kc + 20);
        }
        COMPUTE16(buf)
        if (more) {
            STS_A16(buf ^ 1)
            float bv[8] = {rb0.x, rb0.y, rb0.z, rb0.w, rb1.x, rb1.y, rb1.z, rb1.w};
#pragma unroll
            for (int i = 0; i < 8; i++) Bs[buf ^ 1][tk8 + i][ty] = bv[i];
        }
        __syncthreads();
        buf ^= 1;
    }
#pragma unroll
    for (int p = 0; p < 4; p++) {
        int R = m0 + mwb + 2 * p;
        int x = R >> 6, l = R & 63;
        size_t base = ((size_t)(b * 256 + x) * 256) * 64;
#pragma unroll
        for (int q = 0; q < 8; q++) {
            float lo, hi; UNPK2(lo, hi, acc[p][q]);
            int y = n0 + nwb + (q < 4 ? q : 28 + q);
            sout[base + (size_t)y * 64 + l]     = lo;
            sout[base + (size_t)y * 64 + l + 1] = hi;
        }
    }
}

// ---------------- K6: fused log_softmax + forward + Viterbi + numerator ------
// R13 version (proven fastest scan): sTE float4 + PACK2, pbuf dup'd, vbuf plain.
__global__ void __launch_bounds__(256) k_scan(const float* __restrict__ sflat,
                                              const int* __restrict__ labels,
                                              const float* __restrict__ trans,
                                              const float* __restrict__ startT,
                                              const float* __restrict__ endT) {
    __shared__ float4 sTE[64 * 32];       // [j][kpair] = (t0,t1,e0,e1)  32 KB
    __shared__ float sS[64], sEn[64];
    __shared__ float pbuf[8][2][128];
    __shared__ float vbuf[8][2][64];
    int tid = threadIdx.x;
    for (int i = tid; i < 2048; i += 256) {
        int j = i >> 5, kp = (i & 31) * 2;
        sTE[i] = make_float4(trans[j * 64 + kp], trans[j * 64 + kp + 1],
                             g_expT[j * 64 + kp], g_expT[j * 64 + kp + 1]);
    }
    if (tid < 64) { sS[tid] = startT[tid]; sEn[tid] = endT[tid]; }
    __syncthreads();
    int w = tid >> 5, lane = tid & 31;
    int m = blockIdx.x * 8 + w;
    int k0 = 2 * lane;
    int len = g_len[m >> 8];
    const float* sp   = sflat + (size_t)m * Nn * Ll;
    const int*   tg   = labels + m * Nn;
    float*       hist = g_hist + (size_t)m * Nn * Ll;
    float a0, a1, v0, v1;
    float num;
    int prev;
    {   // t = 0
        float s0 = sp[k0], s1 = sp[k0 + 1];
        float se = __expf(s0) + __expf(s1);
#pragma unroll
        for (int o = 16; o; o >>= 1) se += __shfl_xor_sync(FULLMASK, se, o);
        float lse = __logf(se);
        prev = tg[0];
        float cand = (prev & 1) ? s1 : s0;
        float sv = __shfl_sync(FULLMASK, cand, prev >> 1);
        num = sS[prev] + (sv - lse);
        a0 = sS[k0] + (s0 - lse); a1 = sS[k0 + 1] + (s1 - lse);
        v0 = a0; v1 = a1;
        *(float2*)&hist[k0] = make_float2(v0, v1);
    }
    for (int t = 1; t < len; t++) {
        float s0 = sp[t * 64 + k0], s1 = sp[t * 64 + k0 + 1];
        float se = __expf(s0) + __expf(s1);
#pragma unroll
        for (int o = 16; o; o >>= 1) se += __shfl_xor_sync(FULLMASK, se, o);
        float lse = __logf(se);
        // numerator (gold path)
        int tt = tg[t];
        float cand = (tt & 1) ? s1 : s0;
        float sv = __shfl_sync(FULLMASK, cand, tt >> 1);
        float4 teg = sTE[prev * 32 + (tt >> 1)];
        num += (sv - lse) + ((tt & 1) ? teg.y : teg.x);
        prev = tt;
        float etx = s0 - lse, ety = s1 - lse;
        // forward shift
        float mx = fmaxf(a0, a1);
#pragma unroll
        for (int o = 16; o; o >>= 1) mx = fmaxf(mx, __shfl_xor_sync(FULLMASK, mx, o));
        float p0 = __expf(a0 - mx), p1 = __expf(a1 - mx);
        int pb = t & 1;
        *(float4*)&pbuf[w][pb][4 * lane] = make_float4(p0, p0, p1, p1);
        *(float2*)&vbuf[w][pb][2 * lane] = make_float2(v0, v1);
        __syncwarp();
        unsigned long long q = 0ull;
        float b0 = -1e30f, b1 = -1e30f;
#pragma unroll
        for (int jj = 0; jj < 16; jj++) {
            float4 v4      = *(const float4*)&vbuf[w][pb][4 * jj];
            ulonglong2 pd0 = *(const ulonglong2*)&pbuf[w][pb][8 * jj];
            ulonglong2 pd1 = *(const ulonglong2*)&pbuf[w][pb][8 * jj + 4];
            int j0 = 4 * jj;
            {
                float4 te2 = sTE[(j0 + 0) * 32 + lane];
                unsigned long long e2; PACK2(e2, te2.z, te2.w);
                FMA2(q, pd0.x, e2);
                b0 = fmaxf(b0, v4.x + te2.x); b1 = fmaxf(b1, v4.x + te2.y);
            }
            {
                float4 te2 = sTE[(j0 + 1) * 32 + lane];
                unsigned long long e2; PACK2(e2, te2.z, te2.w);
                FMA2(q, pd0.y, e2);
                b0 = fmaxf(b0, v4.y + te2.x); b1 = fmaxf(b1, v4.y + te2.y);
            }
            {
                float4 te2 = sTE[(j0 + 2) * 32 + lane];
                unsigned long long e2; PACK2(e2, te2.z, te2.w);
                FMA2(q, pd1.x, e2);
                b0 = fmaxf(b0, v4.z + te2.x); b1 = fmaxf(b1, v4.z + te2.y);
            }
            {
                float4 te2 = sTE[(j0 + 3) * 32 + lane];
                unsigned long long e2; PACK2(e2, te2.z, te2.w);
                FMA2(q, pd1.y, e2);
                b0 = fmaxf(b0, v4.w + te2.x); b1 = fmaxf(b1, v4.w + te2.y);
            }
        }
        float q0, q1; UNPK2(q0, q1, q);
        v0 = b0 + etx; v1 = b1 + ety;
        a0 = mx + __logf(q0) + etx;
        a1 = mx + __logf(q1) + ety;
        *(float2*)&hist[t * 64 + k0] = make_float2(v0, v1);
    }
    // den + num writeback
    float z0 = a0 + sEn[k0], z1 = a1 + sEn[k0 + 1];
    float mx = fmaxf(z0, z1);
#pragma unroll
    for (int o = 16; o; o >>= 1) mx = fmaxf(mx, __shfl_xor_sync(FULLMASK, mx, o));
    float e = __expf(z0 - mx) + __expf(z1 - mx);
#pragma unroll
    for (int o = 16; o; o >>= 1) e += __shfl_xor_sync(FULLMASK, e, o);
    if (lane == 0) {
        g_den[m] = mx + __logf(e);
        g_num[m] = num + sEn[prev];
    }
}

// ---------------- K7: Viterbi backtrace ----------------
__global__ void __launch_bounds__(256) k_bt(const float* __restrict__ trans,
                                            const float* __restrict__ endT,
                                            float* __restrict__ dec_out) {
    __shared__ float sT[64 * 65];
    __shared__ float sEn[64];
    int tid = threadIdx.x;
    for (int i = tid; i < 4096; i += 256) { int j = i >> 6, k = i & 63; sT[j * 65 + k] = trans[i]; }
    if (tid < 64) sEn[tid] = endT[tid];
    __syncthreads();
    int m = blockIdx.x * 8 + (tid >> 5), lane = tid & 31, k1 = lane, k2 = lane + 32;
    int len = g_len[m >> 8];
    const float* hist = g_hist + (size_t)m * Nn * Ll;
    float* dec = dec_out + (size_t)m * Nn;
    float f1 = hist[(len - 1) * 64 + k1] + sEn[k1];
    float f2 = hist[(len - 1) * 64 + k2] + sEn[k2];
    float bv; int bi;
    if (f2 > f1) { bv = f2; bi = k2; } else { bv = f1; bi = k1; }
#pragma unroll
    for (int o = 16; o; o >>= 1) {
        float ov = __shfl_xor_sync(FULLMASK, bv, o);
        int   oi = __shfl_xor_sync(FULLMASK, bi, o);
        if (ov > bv || (ov == bv && oi < bi)) { bv = ov; bi = oi; }
    }
    int cur = bi;
    for (int j = len - 1 + lane; j < Nn; j += 32) dec[j] = (float)cur;
    for (int t = len - 1; t >= 1; t--) {
        float h1v = hist[(t - 1) * 64 + k1] + sT[k1 * 65 + cur];
        float h2v = hist[(t - 1) * 64 + k2] + sT[k2 * 65 + cur];
        float bv2; int bi2;
        if (h2v > h1v) { bv2 = h2v; bi2 = k2; } else { bv2 = h1v; bi2 = k1; }
#pragma unroll
        for (int o = 16; o; o >>= 1) {
            float ov = __shfl_xor_sync(FULLMASK, bv2, o);
            int   oi = __shfl_xor_sync(FULLMASK, bi2, o);
            if (ov > bv2 || (ov == bv2 && oi < bi2)) { bv2 = ov; bi2 = oi; }
        }
        cur = bi2;
        if (lane == 0) dec[t - 1] = (float)cur;
    }
}

// ---------------- K8: loss reduction ----------------
__global__ void k_loss(float* __restrict__ out) {
    __shared__ float sm[256];
    int tid = threadIdx.x;
    float s = 0.f;
    for (int i = 0; i < 16; i++) {
        int m = tid * 16 + i;
        bool w = (m & 255) < g_len[m >> 8];
        if (w) s += g_num[m] - g_den[m];
    }
    sm[tid] = s;
    __syncthreads();
    for (int st = 128; st; st >>= 1) { if (tid < st) sm[tid] += sm[tid + st]; __syncthreads(); }
    if (tid == 0) out[0] = -sm[0];
}

// ---------------- launch ----------------
extern "C" void kernel_launch(void* const* d_in, const int* in_sizes, int n_in,
                              void* d_out, int out_size) {
    (void)in_sizes; (void)n_in; (void)out_size;
    const float* input  = (const float*)d_in[0];
    const void*  mask   = d_in[1];
    const int*   labels = (const int*)d_in[2];
    const float* Wh     = (const float*)d_in[3];
    const float* bh     = (const float*)d_in[4];
    const float* Wd     = (const float*)d_in[5];
    const float* bd     = (const float*)d_in[6];
    const float* Wb     = (const float*)d_in[7];
    const float* startT = (const float*)d_in[8];
    const float* trans  = (const float*)d_in[9];
    const float* endT   = (const float*)d_in[10];

    float* out     = (float*)d_out;
    float* s_out   = out + 1;
    float* dec_out = out + 1 + (size_t)Mm * Nn * Ll;

    k_pre  <<<1, 256>>>(mask, trans);
    k_mlp  <<<160 + 5776, 256>>>(input, Wh, bh, Wd, bd, Wb);   // MLP + padW merged
    k_gemmU<<<dim3(152, 32),     256>>>();
    k_gemmS<<<dim3(2, 128, 16),  256>>>(s_out);
    k_scan <<<512, 256>>>(s_out, labels, trans, startT, endT);
    k_bt   <<<512, 256>>>(trans, endT, dec_out);
    k_loss <<<1, 256>>>(out);
}